// round 9
// baseline (speedup 1.0000x reference)
#include <cuda_runtime.h>
#include <stdint.h>

// Problem constants (fixed by the reference)
#define B_     8192
#define W0_    1024
#define R_     8
#define G_     1024
#define WORDS  (B_ / 32)          // 256 batch words
#define OUTW   (W0_ + R_ * G_)    // 9216 output columns
#define NT     512                // threads per block

#define ONE_F  0x3F800000u        // bit pattern of 1.0f

// ---------------------------------------------------------------------------
// Fused kernel, one block per batch word (32 samples), 512 threads.
// Per-word column state (9216 uint32 = 36 KB) in shared memory.
//
// R9 change vs R8: the gate parameters (choices int4 + two tt float4 per
// thread, covering 2 adjacent gates) are DOUBLE-BUFFERED in registers.
// Row r+1's params are loaded at the top of row r's body and fly over the
// compute + barrier + 16-STG store pass, so the row-phase critical path
// drops from [L2 LDG ~300-600cyc + LDS chain] to [LDS ~29cyc + LOP + STS].
// This was the store-stream duty-cycle hole (DRAM idle 41% at R8).
// ---------------------------------------------------------------------------

// Store 1024 consecutive columns [c0base, c0base+1024) of batch word w.
// Threads 0..255 handle batch rows 0..15, threads 256..511 rows 16..31.
// Integer-ALU float construction (bit ? 0x3F800000 : 0), no I2F.
__device__ __forceinline__ void unpack_1024(const uint32_t* __restrict__ s,
                                            float* __restrict__ out,
                                            int w, int c0base, int tid) {
    const int half = tid >> 8;                 // 0 or 1
    const int t2   = tid & 255;
    const int c0   = c0base + t2 * 4;          // 4 consecutive cols
    const uint4 bv = *reinterpret_cast<const uint4*>(&s[c0]);

    uint32_t* base = reinterpret_cast<uint32_t*>(out)
                   + (size_t)(w * 32 + half * 16) * OUTW + c0;

    #pragma unroll
    for (int i = 0; i < 16; ++i) {
        const int bit = half * 16 + i;
        uint4 v;
        v.x = ((bv.x >> bit) & 1u) * ONE_F;
        v.y = ((bv.y >> bit) & 1u) * ONE_F;
        v.z = ((bv.z >> bit) & 1u) * ONE_F;
        v.w = ((bv.w >> bit) & 1u) * ONE_F;
        __stcs(reinterpret_cast<uint4*>(base + (size_t)i * OUTW), v);
    }
}

__global__ __launch_bounds__(NT, 2) void gator_fused_kernel(
    const float* __restrict__ x,        // [B, W0] 0/1 floats
    const float* __restrict__ gates,    // [R, G, 4]
    const int*   __restrict__ choices,  // [R, G, 2]
    float*       __restrict__ out)      // [B, OUTW]
{
    __shared__ uint32_t s[OUTW];        // 36864 bytes

    const int w    = blockIdx.x;        // batch word (32 samples)
    const int tid  = threadIdx.x;
    const int warp = tid >> 5;          // 0..15
    const int lane = tid & 31;

    const int4*   ch4 = reinterpret_cast<const int4*>(choices);  // [R*512]
    const float4* g4  = reinterpret_cast<const float4*>(gates);  // [R*1024]

    // Prefetch row 0 params (thread t owns gates 2t and 2t+1; all coalesced).
    int4   ch = __ldg(ch4 + tid);
    float4 ta = __ldg(g4 + 2 * tid);
    float4 tb = __ldg(g4 + 2 * tid + 1);

    // ---- pack: x[w*32 .. w*32+31, :] -> ballot bits ----------------------
    // Lane = sample; warp j covers columns [j*64, j*64+64). Per-lane float4
    // loads stream sequentially -> 8x L1 reuse of each 128B line.
    {
        const float4* row = reinterpret_cast<const float4*>(
            x + (size_t)(w * 32 + lane) * W0_);
        const int colbase = warp * 64;
        #pragma unroll 4
        for (int it = 0; it < 16; ++it) {
            const int c = colbase + it * 4;
            float4 v = row[c >> 2];
            uint32_t b0 = __ballot_sync(0xffffffffu, v.x > 0.5f);
            uint32_t b1 = __ballot_sync(0xffffffffu, v.y > 0.5f);
            uint32_t b2 = __ballot_sync(0xffffffffu, v.z > 0.5f);
            uint32_t b3 = __ballot_sync(0xffffffffu, v.w > 0.5f);
            if (lane == 0) {
                s[c + 0] = b0;
                s[c + 1] = b1;
                s[c + 2] = b2;
                s[c + 3] = b3;
            }
        }
    }
    __syncthreads();

    // ---- start the output stream with the x columns ----------------------
    unpack_1024(s, out, w, 0, tid);

    // ---- 8 gate rows: prefetch next params, compute 2 gates, store -------
    #pragma unroll
    for (int r = 0; r < R_; ++r) {
        // Issue row r+1's param loads now; they fly over this row's compute,
        // barrier, and store pass (~1000+ cyc of cover).
        int4 chn; float4 tan, tbn;
        if (r < R_ - 1) {
            chn = __ldg(ch4 + (r + 1) * 512 + tid);
            tan = __ldg(g4 + (r + 1) * 1024 + 2 * tid);
            tbn = __ldg(g4 + (r + 1) * 1024 + 2 * tid + 1);
        }

        const int outbase = W0_ + r * G_;

        // Gate 2t: inputs ch.x/ch.y, table ta. Gate 2t+1: ch.z/ch.w, tb.
        uint32_t o0, o1;
        {
            const uint32_t a  = s[ch.x];
            const uint32_t bb = s[ch.y];
            const uint32_t m0 = (ta.x > 0.5f) ? 0xffffffffu : 0u;
            const uint32_t m1 = (ta.y > 0.5f) ? 0xffffffffu : 0u;
            const uint32_t m2 = (ta.z > 0.5f) ? 0xffffffffu : 0u;
            const uint32_t m3 = (ta.w > 0.5f) ? 0xffffffffu : 0u;
            o0 = (m0 & ~a & ~bb) | (m1 & ~a & bb)
               | (m2 &  a & ~bb) | (m3 &  a &  bb);
        }
        {
            const uint32_t a  = s[ch.z];
            const uint32_t bb = s[ch.w];
            const uint32_t m0 = (tb.x > 0.5f) ? 0xffffffffu : 0u;
            const uint32_t m1 = (tb.y > 0.5f) ? 0xffffffffu : 0u;
            const uint32_t m2 = (tb.z > 0.5f) ? 0xffffffffu : 0u;
            const uint32_t m3 = (tb.w > 0.5f) ? 0xffffffffu : 0u;
            o1 = (m0 & ~a & ~bb) | (m1 & ~a & bb)
               | (m2 &  a & ~bb) | (m3 &  a &  bb);
        }
        // Both outputs adjacent -> one STS.64.
        uint2 ov; ov.x = o0; ov.y = o1;
        *reinterpret_cast<uint2*>(&s[outbase + 2 * tid]) = ov;

        __syncthreads();

        // Stream out this row; next row's compute has its params in regs and
        // writes a disjoint smem region, so it runs under these stores.
        unpack_1024(s, out, w, outbase, tid);

        ch = chn; ta = tan; tb = tbn;
    }
}

// ---------------------------------------------------------------------------
// Single launch; no allocation, no sync -> graph-capturable.
// Inputs (metadata order): x f32 [8192,1024], gates f32 [8,1024,4],
// choices i32 [8,1024,2]. Output f32 [8192, 9216].
// ---------------------------------------------------------------------------
extern "C" void kernel_launch(void* const* d_in, const int* in_sizes, int n_in,
                              void* d_out, int out_size) {
    const float* x       = (const float*)d_in[0];
    const float* gates   = (const float*)d_in[1];
    const int*   choices = (const int*)  d_in[2];
    float*       out     = (float*)d_out;

    gator_fused_kernel<<<WORDS, NT>>>(x, gates, choices, out);
}